// round 2
// baseline (speedup 1.0000x reference)
#include <cuda_runtime.h>

// AtomicConv edge aggregation, round 2.
// Kernel 1: zero the output AND precompute per-node one-hot type (int8, L1-resident).
// Kernel 2: 4 edges/thread, phase-batched gathers for MLP, float4 RED to out.

#define MAX_NODES (1 << 20)
__device__ signed char g_type[MAX_NODES];

__global__ __launch_bounds__(256) void zero_and_type_kernel(
    float4* __restrict__ out, int n4,
    const float* __restrict__ feat, const float* __restrict__ ftu, int n_nodes)
{
    int i = blockIdx.x * blockDim.x + threadIdx.x;
    if (i < n4) out[i] = make_float4(0.f, 0.f, 0.f, 0.f);
    if (i < n_nodes) {
        float f = __ldg(feat + i);
        signed char t = -1;
        #pragma unroll
        for (int j = 0; j < 8; j++)
            if (f == __ldg(ftu + j)) t = (signed char)j;
        g_type[i] = t;
    }
}

__device__ __forceinline__ float edge_weight(float d, float cut, float mean,
                                             float sc, float hpoc) {
    // 0.5*(cos(pi*d/cut)+1) == cos^2(pi*d/(2*cut))
    float c = __cosf(d * hpoc);
    float cv = c * c;
    cv = (d <= cut) ? cv : 0.f;
    float dm = d - mean;
    return cv * __expf(-sc * dm * dm);
}

constexpr int EPT = 4;

__global__ __launch_bounds__(256) void acnn_edge_kernel(
    const float* __restrict__ dist,   // (E)
    const float* __restrict__ rp,     // (16,3) [cutoff, mean, scaling]
    const int*   __restrict__ src,    // (E)
    const int*   __restrict__ dstv,   // (E)
    float*       __restrict__ out,    // (N,128)
    int n_edges, int epb)
{
    int base = blockIdx.x * (256 * EPT) + threadIdx.x;

    int  e[EPT], s[EPT], dn[EPT], t[EPT];
    bool act[EPT];

    // Phase 1: batched index loads (coalesced, 4 outstanding each)
    #pragma unroll
    for (int i = 0; i < EPT; i++) {
        e[i] = base + i * 256;
        act[i] = (e[i] < n_edges);
    }
    #pragma unroll
    for (int i = 0; i < EPT; i++) if (act[i]) s[i]  = __ldg(src  + e[i]);
    #pragma unroll
    for (int i = 0; i < EPT; i++) if (act[i]) dn[i] = __ldg(dstv + e[i]);

    // Phase 2: batched random type gathers from the 20KB L1-resident table
    #pragma unroll
    for (int i = 0; i < EPT; i++) {
        if (act[i]) {
            t[i] = (int)g_type[s[i]];
            act[i] = (t[i] >= 0);
        }
    }

    // Phase 3: per active edge — params, 64B dist load, MUFU, vector RED
    #pragma unroll
    for (int i = 0; i < EPT; i++) {
        if (!act[i]) continue;

        int q = e[i] / epb;            // radial kernel index (uniform-ish per block)
        int r = e[i] - q * epb;
        float cut  = __ldg(rp + 3 * q + 0);
        float mean = __ldg(rp + 3 * q + 1);
        float sc   = __ldg(rp + 3 * q + 2);
        float hpoc = 1.57079632679489662f / cut;   // pi/(2*cut)

        const float4* dp = reinterpret_cast<const float4*>(dist) + (r << 2);
        float4* op = reinterpret_cast<float4*>(out) + ((dn[i] << 5) + (t[i] << 2));

        float4 d4[4];
        #pragma unroll
        for (int k = 0; k < 4; k++) d4[k] = __ldg(dp + k);

        #pragma unroll
        for (int k = 0; k < 4; k++) {
            float4 w;
            w.x = edge_weight(d4[k].x, cut, mean, sc, hpoc);
            w.y = edge_weight(d4[k].y, cut, mean, sc, hpoc);
            w.z = edge_weight(d4[k].z, cut, mean, sc, hpoc);
            w.w = edge_weight(d4[k].w, cut, mean, sc, hpoc);
            atomicAdd(op + k, w);      // RED.128
        }
    }
}

extern "C" void kernel_launch(void* const* d_in, const int* in_sizes, int n_in,
                              void* d_out, int out_size) {
    const float* feat = (const float*)d_in[0];   // (N,1)
    const float* dist = (const float*)d_in[1];   // (E,1)
    const float* rp   = (const float*)d_in[2];   // (16,3)
    const float* ftu  = (const float*)d_in[3];   // (8,)
    const int*   src  = (const int*)d_in[4];     // (E,)
    const int*   dst  = (const int*)d_in[5];     // (E,)
    float* out = (float*)d_out;

    int n_nodes = in_sizes[0];
    int n_edges = in_sizes[1];
    int epb = n_edges / 16;
    int n4 = out_size / 4;

    zero_and_type_kernel<<<(n4 + 255) / 256, 256>>>(
        (float4*)out, n4, feat, ftu, n_nodes);

    int per_block = 256 * EPT;
    acnn_edge_kernel<<<(n_edges + per_block - 1) / per_block, 256>>>(
        dist, rp, src, dst, out, n_edges, epb);
}